// round 15
// baseline (speedup 1.0000x reference)
#include <cuda_runtime.h>
#include <cuda_bf16.h>
#include <cstdint>

typedef unsigned int u32;

#define NORM 0.35355339059327379f   // 64^-0.25
#define RATIO 0.0625f               // 256^-0.5
#define TILE 128
#define NTILES 512
#define KBLOCKS 148

// scratch (allocation-free rule): per-block z partials + bf16 split of z
__device__ float g_zpart[(size_t)KBLOCKS * 65 * 256];   // [block][n(0..64)][feat]
__device__ __nv_bfloat16 g_zbh[72 * 256];               // rows 65..71 stay zero-init
__device__ __nv_bfloat16 g_zbl[72 * 256];

// ---------------- helpers ----------------
__device__ __forceinline__ u32 smem_u32(const void* p) {
    u32 a; asm("{ .reg .u64 t; cvta.to.shared.u64 t, %1; cvt.u32.u64 %0, t; }" : "=r"(a) : "l"(p)); return a;
}
__device__ __forceinline__ void mma_bf16(float* d, const u32* a, const u32* b) {
    asm volatile(
        "mma.sync.aligned.m16n8k16.row.col.f32.bf16.bf16.f32 "
        "{%0,%1,%2,%3}, {%4,%5,%6,%7}, {%8,%9}, {%0,%1,%2,%3};"
        : "+f"(d[0]), "+f"(d[1]), "+f"(d[2]), "+f"(d[3])
        : "r"(a[0]), "r"(a[1]), "r"(a[2]), "r"(a[3]), "r"(b[0]), "r"(b[1]));
}
__device__ __forceinline__ void ldmx2t(u32& r0, u32& r1, u32 addr) {
    asm volatile("ldmatrix.sync.aligned.m8n8.x2.trans.shared.b16 {%0,%1}, [%2];"
        : "=r"(r0), "=r"(r1) : "r"(addr));
}
__device__ __forceinline__ void split2(float x, float y, u32& h, u32& l) {
    __nv_bfloat162 hh = __floats2bfloat162_rn(x, y);
    float2 hf = __bfloat1622float2(hh);
    __nv_bfloat162 ll = __floats2bfloat162_rn(x - hf.x, y - hf.y);
    h = *reinterpret_cast<u32*>(&hh);
    l = *reinterpret_cast<u32*>(&ll);
}
__device__ __forceinline__ void split1(float x, uint16_t& h, uint16_t& l) {
    __nv_bfloat16 bh = __float2bfloat16(x);
    h = __bfloat16_as_ushort(bh);
    l = __bfloat16_as_ushort(__float2bfloat16(x - __bfloat162float(bh)));
}

// stage [nrows x 64] fp32 (RAW) -> bf16 hi/lo, row stride 144 B; optional sumsq
template<int STEP>
__device__ __forceinline__ void stage64(char* dh, char* dl, const float* src,
                                        int nrows, float* sn, int tid) {
    const float4* sp = reinterpret_cast<const float4*>(src);
    int total = nrows * 16;
    for (int idx = tid; idx < total; idx += STEP) {
        int row = idx >> 4, c4 = idx & 15;
        float4 f = sp[idx];
        if (sn) {
            float ps = f.x * f.x + f.y * f.y + f.z * f.z + f.w * f.w;
#pragma unroll
            for (int s = 8; s >= 1; s >>= 1) ps += __shfl_xor_sync(0xffffffffu, ps, s);
            if ((tid & 15) == 0) sn[row] = ps;
        }
        u32 h0, l0, h1, l1;
        split2(f.x, f.y, h0, l0);
        split2(f.z, f.w, h1, l1);
        *(uint2*)(dh + row * 144 + c4 * 8) = make_uint2(h0, h1);
        *(uint2*)(dl + row * 144 + c4 * 8) = make_uint2(l0, l1);
    }
}

// reduce 148 partials -> bf16 split (replaces zero+zsplit kernels)
__global__ void reduce_kernel() {
    int t = blockIdx.x * blockDim.x + threadIdx.x;
    if (t >= 65 * 256) return;
    float s = 0.0f;
    const float* p = g_zpart + t;
    for (int b = 0; b < KBLOCKS; b++) s += p[(size_t)b * (65 * 256)];
    __nv_bfloat16 h = __float2bfloat16(s);
    g_zbh[t] = h;
    g_zbl[t] = __float2bfloat16(s - __bfloat162float(h));
}

// ======================= kside: 256 threads, clean strides, STG partials =======================
#define KS_PTH 0
#define KS_PTL 36864
#define KS_KNH 73728
#define KS_KNL 92160
#define KS_KHH 110592
#define KS_KHL 145408
#define KS_VTH 180224
#define KS_VTL 201984
#define KS_SN  223744
#define KSMEM  224256

__global__ __launch_bounds__(256, 1) void kside_kernel(
    const float* __restrict__ kin, const float* __restrict__ vin,
    const float* __restrict__ proj)
{
    extern __shared__ char sm[];
    const int tid = threadIdx.x;
    const int lane = tid & 31, w = tid >> 5;
    const int g = lane >> 2, tg = lane & 3;
    float* sn = reinterpret_cast<float*>(sm + KS_SN);
    const u32 khh_u = smem_u32(sm) + KS_KHH;
    const u32 khl_u = smem_u32(sm) + KS_KHL;

    stage64<256>(sm + KS_PTH, sm + KS_PTL, proj, 256, nullptr, tid);
    // vT constant rows: n=64 -> ones, n=65..79 -> zero (set once)
    for (int i = tid; i < 16 * 128; i += 256) {
        int n = 64 + (i >> 7), k = i & 127;
        uint16_t hv = (n == 64) ? (uint16_t)0x3F80 : (uint16_t)0;
        *(uint16_t*)(sm + KS_VTH + n * 272 + k * 2) = hv;
        *(uint16_t*)(sm + KS_VTL + n * 272 + k * 2) = 0;
    }

    float zacc[5][4][4];
#pragma unroll
    for (int m = 0; m < 5; m++)
#pragma unroll
        for (int j = 0; j < 4; j++)
#pragma unroll
            for (int r = 0; r < 4; r++) zacc[m][j][r] = 0.0f;

    for (int tile = blockIdx.x; tile < NTILES; tile += KBLOCKS) {
        __syncthreads();
        stage64<256>(sm + KS_KNH, sm + KS_KNL, kin + (size_t)tile * TILE * 64, 128, sn, tid);
        {   // stage v transposed: vT[n=col][krow]
            const float4* sp = reinterpret_cast<const float4*>(vin + (size_t)tile * TILE * 64);
            for (int idx = tid; idx < 2048; idx += 256) {
                int row = idx >> 4, c4 = idx & 15;
                float4 f = sp[idx];
                float vv[4] = {f.x, f.y, f.z, f.w};
#pragma unroll
                for (int j = 0; j < 4; j++) {
                    uint16_t h, l; split1(vv[j], h, l);
                    int n = c4 * 4 + j;
                    *(uint16_t*)(sm + KS_VTH + n * 272 + row * 2) = h;
                    *(uint16_t*)(sm + KS_VTL + n * 272 + row * 2) = l;
                }
            }
        }
        __syncthreads();

        for (int h = 0; h < 2; h++) {
            // ---- dash: D[16 rows][128 feats] per warp ----
            float dD[16][4];
#pragma unroll
            for (int nt = 0; nt < 16; nt++)
#pragma unroll
                for (int r = 0; r < 4; r++) dD[nt][r] = 0.0f;
#pragma unroll
            for (int ks = 0; ks < 4; ks++) {
                u32 ab = (u32)((w * 16 + g) * 144 + ks * 32 + tg * 4);
                u32 ah[4] = { *(u32*)(sm + KS_KNH + ab),       *(u32*)(sm + KS_KNH + ab + 8 * 144),
                              *(u32*)(sm + KS_KNH + ab + 16),  *(u32*)(sm + KS_KNH + ab + 8 * 144 + 16) };
                u32 al[4] = { *(u32*)(sm + KS_KNL + ab),       *(u32*)(sm + KS_KNL + ab + 8 * 144),
                              *(u32*)(sm + KS_KNL + ab + 16),  *(u32*)(sm + KS_KNL + ab + 8 * 144 + 16) };
#pragma unroll
                for (int nt = 0; nt < 16; nt++) {
                    u32 bb = (u32)((h * 128 + nt * 8 + g) * 144 + ks * 32 + tg * 4);
                    u32 bh[2] = { *(u32*)(sm + KS_PTH + bb), *(u32*)(sm + KS_PTH + bb + 16) };
                    u32 bl[2] = { *(u32*)(sm + KS_PTL + bb), *(u32*)(sm + KS_PTL + bb + 16) };
                    mma_bf16(dD[nt], ah, bh);
                    mma_bf16(dD[nt], ah, bl);
                    mma_bf16(dD[nt], al, bh);
                }
            }
            // ---- epilogue: exp, split, store k_hat[krow][feat-in-half] ----
            {
                float s0 = sn[w * 16 + g], s1 = sn[w * 16 + 8 + g];
#pragma unroll
                for (int nt = 0; nt < 16; nt++) {
                    float e0 = RATIO * __expf(NORM * dD[nt][0] - 0.0625f * s0);
                    float e1 = RATIO * __expf(NORM * dD[nt][1] - 0.0625f * s0);
                    float e2 = RATIO * __expf(NORM * dD[nt][2] - 0.0625f * s1);
                    float e3 = RATIO * __expf(NORM * dD[nt][3] - 0.0625f * s1);
                    u32 h01, l01, h23, l23;
                    split2(e0, e1, h01, l01);
                    split2(e2, e3, h23, l23);
                    u32 o0 = (u32)((w * 16 + g) * 272 + (nt * 8 + tg * 2) * 2);
                    u32 o1 = (u32)((w * 16 + 8 + g) * 272 + (nt * 8 + tg * 2) * 2);
                    *(u32*)(sm + KS_KHH + o0) = h01;
                    *(u32*)(sm + KS_KHH + o1) = h23;
                    *(u32*)(sm + KS_KHL + o0) = l01;
                    *(u32*)(sm + KS_KHL + o1) = l23;
                }
            }
            __syncthreads();
            // ---- z-mma: zT[80 vn][feat half] += vT @ k_hat ----
#pragma unroll
            for (int ks = 0; ks < 8; ks++) {
                u32 bh[2][2], bl[2][2];
#pragma unroll
                for (int j = 0; j < 2; j++) {
                    u32 la = (u32)((ks * 16 + (lane & 15)) * 272 + (w * 16 + j * 8) * 2);
                    ldmx2t(bh[j][0], bh[j][1], khh_u + la);
                    ldmx2t(bl[j][0], bl[j][1], khl_u + la);
                }
#pragma unroll
                for (int mt = 0; mt < 5; mt++) {
                    u32 ab = (u32)((mt * 16 + g) * 272 + ks * 32 + tg * 4);
                    u32 ah[4] = { *(u32*)(sm + KS_VTH + ab),      *(u32*)(sm + KS_VTH + ab + 8 * 272),
                                  *(u32*)(sm + KS_VTH + ab + 16), *(u32*)(sm + KS_VTH + ab + 8 * 272 + 16) };
                    u32 al[4] = { *(u32*)(sm + KS_VTL + ab),      *(u32*)(sm + KS_VTL + ab + 8 * 272),
                                  *(u32*)(sm + KS_VTL + ab + 16), *(u32*)(sm + KS_VTL + ab + 8 * 272 + 16) };
#pragma unroll
                    for (int j = 0; j < 2; j++) {
                        float* acc = zacc[mt][h * 2 + j];
                        mma_bf16(acc, ah, bh[j]);
                        mma_bf16(acc, ah, bl[j]);
                        mma_bf16(acc, al, bh[j]);
                    }
                }
            }
            __syncthreads();
        }
    }

    // flush zT accumulators: plain per-block partial stores (no atomics)
    {
        float* zp = g_zpart + (size_t)blockIdx.x * (65 * 256);
#pragma unroll
        for (int mt = 0; mt < 5; mt++) {
            int vn0 = mt * 16 + g, vn1 = vn0 + 8;
#pragma unroll
            for (int jj = 0; jj < 4; jj++) {
                int f0 = (jj >> 1) * 128 + w * 16 + (jj & 1) * 8 + tg * 2;
                if (vn0 < 65)
                    *(float2*)&zp[vn0 * 256 + f0] = make_float2(zacc[mt][jj][0], zacc[mt][jj][1]);
                if (vn1 < 65)
                    *(float2*)&zp[vn1 * 256 + f0] = make_float2(zacc[mt][jj][2], zacc[mt][jj][3]);
            }
        }
    }
}

// ======================= qside: 512 threads, 2 row-tiles per block =======================
#define QS_PTH 0
#define QS_PTL 36864
#define QS_QNH 73728
#define QS_QNL 92160
#define QS_ZH  110592
#define QS_ZL  148608
#define QS_SN  186624
#define QSMEM  187136

__global__ __launch_bounds__(512, 1) void qside_kernel(
    const float* __restrict__ qin, const float* __restrict__ proj,
    float* __restrict__ out)
{
    extern __shared__ char sm[];
    const int tid = threadIdx.x;
    const int lane = tid & 31, w = tid >> 5;
    const int g = lane >> 2, tg = lane & 3;
    const int wr = w & 7, wh = w >> 3;
    float* sn = reinterpret_cast<float*>(sm + QS_SN);

    // stage P and zT once per block (amortized over 2 row-tiles)
    stage64<512>(sm + QS_PTH, sm + QS_PTL, proj, 256, nullptr, tid);
    for (int i = tid; i < 72 * 128; i += 512) {
        int n = i >> 7, c = i & 127;
        *(u32*)(sm + QS_ZH + n * 528 + c * 4) = reinterpret_cast<const u32*>(g_zbh)[i];
        *(u32*)(sm + QS_ZL + n * 528 + c * 4) = reinterpret_cast<const u32*>(g_zbl)[i];
    }

    for (int it = 0; it < 2; it++) {
        const int tile = blockIdx.x * 2 + it;
        __syncthreads();   // previous iteration's scratch reads / first-iter stage order
        stage64<512>(sm + QS_QNH, sm + QS_QNL, qin + (size_t)tile * TILE * 64, 128, sn, tid);
        __syncthreads();

        float wD[9][4];
#pragma unroll
        for (int nt = 0; nt < 9; nt++)
#pragma unroll
            for (int r = 0; r < 4; r++) wD[nt][r] = 0.0f;

        const float s0 = sn[wr * 16 + g], s1 = sn[wr * 16 + 8 + g];

#pragma unroll
        for (int chunk = 0; chunk < 2; chunk++) {
            const int fbase = wh * 128 + chunk * 64;
            float dD[8][4];
#pragma unroll
            for (int nt = 0; nt < 8; nt++)
#pragma unroll
                for (int r = 0; r < 4; r++) dD[nt][r] = 0.0f;
#pragma unroll
            for (int ks = 0; ks < 4; ks++) {
                u32 ab = (u32)((wr * 16 + g) * 144 + ks * 32 + tg * 4);
                u32 ah[4] = { *(u32*)(sm + QS_QNH + ab),      *(u32*)(sm + QS_QNH + ab + 8 * 144),
                              *(u32*)(sm + QS_QNH + ab + 16), *(u32*)(sm + QS_QNH + ab + 8 * 144 + 16) };
                u32 al[4] = { *(u32*)(sm + QS_QNL + ab),      *(u32*)(sm + QS_QNL + ab + 8 * 144),
                              *(u32*)(sm + QS_QNL + ab + 16), *(u32*)(sm + QS_QNL + ab + 8 * 144 + 16) };
#pragma unroll
                for (int nt = 0; nt < 8; nt++) {
                    u32 bb = (u32)((fbase + nt * 8 + g) * 144 + ks * 32 + tg * 4);
                    u32 bh[2] = { *(u32*)(sm + QS_PTH + bb), *(u32*)(sm + QS_PTH + bb + 16) };
                    u32 bl[2] = { *(u32*)(sm + QS_PTL + bb), *(u32*)(sm + QS_PTL + bb + 16) };
                    mma_bf16(dD[nt], ah, bh);
                    mma_bf16(dD[nt], ah, bl);
                    mma_bf16(dD[nt], al, bh);
                }
            }
            u32 qh0[8], qh1[8], ql0[8], ql1[8];
#pragma unroll
            for (int nt = 0; nt < 8; nt++) {
                float e0 = RATIO * __expf(NORM * dD[nt][0] - 0.0625f * s0);
                float e1 = RATIO * __expf(NORM * dD[nt][1] - 0.0625f * s0);
                float e2 = RATIO * __expf(NORM * dD[nt][2] - 0.0625f * s1);
                float e3 = RATIO * __expf(NORM * dD[nt][3] - 0.0625f * s1);
                split2(e0, e1, qh0[nt], ql0[nt]);
                split2(e2, e3, qh1[nt], ql1[nt]);
            }
#pragma unroll
            for (int ks = 0; ks < 4; ks++) {
                u32 ah[4] = { qh0[2 * ks], qh1[2 * ks], qh0[2 * ks + 1], qh1[2 * ks + 1] };
                u32 al[4] = { ql0[2 * ks], ql1[2 * ks], ql0[2 * ks + 1], ql1[2 * ks + 1] };
                u32 kb = (u32)(fbase + ks * 16) * 2;
#pragma unroll
                for (int nt = 0; nt < 9; nt++) {
                    u32 bb = (u32)((nt * 8 + g) * 528) + kb + tg * 4;
                    u32 bh[2] = { *(u32*)(sm + QS_ZH + bb), *(u32*)(sm + QS_ZH + bb + 16) };
                    u32 bl[2] = { *(u32*)(sm + QS_ZL + bb), *(u32*)(sm + QS_ZL + bb + 16) };
                    mma_bf16(wD[nt], ah, bh);
                    mma_bf16(wD[nt], ah, bl);
                    mma_bf16(wD[nt], al, bh);
                }
            }
        }

        // ---- cross-half reduction (scratch aliases dead qn region) ----
        __syncthreads();
        float* scratch = reinterpret_cast<float*>(sm + QS_QNH);
        if (wh == 1) {
            float4* sp = reinterpret_cast<float4*>(&scratch[(wr * 32 + lane) * 36]);
#pragma unroll
            for (int nt = 0; nt < 9; nt++)
                sp[nt] = make_float4(wD[nt][0], wD[nt][1], wD[nt][2], wD[nt][3]);
        }
        __syncthreads();
        if (wh == 0) {
            const float4* sp = reinterpret_cast<const float4*>(&scratch[(wr * 32 + lane) * 36]);
#pragma unroll
            for (int nt = 0; nt < 9; nt++) {
                float4 p = sp[nt];
                wD[nt][0] += p.x; wD[nt][1] += p.y; wD[nt][2] += p.z; wD[nt][3] += p.w;
            }
            float den0 = __shfl_sync(0xffffffffu, wD[8][0], lane & 0x1C);
            float den1 = __shfl_sync(0xffffffffu, wD[8][2], lane & 0x1C);
            float di0 = 1.0f / den0, di1 = 1.0f / den1;
            size_t row0 = (size_t)tile * TILE + wr * 16 + g;
            float* ob = out + row0 * 64 + tg * 2;
#pragma unroll
            for (int nt = 0; nt < 8; nt++) {
                *(float2*)(ob + nt * 8)          = make_float2(wD[nt][0] * di0, wD[nt][1] * di0);
                *(float2*)(ob + 8 * 64 + nt * 8) = make_float2(wD[nt][2] * di1, wD[nt][3] * di1);
            }
        }
    }
}

extern "C" void kernel_launch(void* const* d_in, const int* in_sizes, int n_in,
                              void* d_out, int out_size) {
    const float* q = (const float*)d_in[0];
    const float* k = (const float*)d_in[1];
    const float* v = (const float*)d_in[2];
    const float* P = (const float*)d_in[3];
    float* out = (float*)d_out;
    (void)in_sizes; (void)n_in; (void)out_size;

    cudaFuncSetAttribute(kside_kernel, cudaFuncAttributeMaxDynamicSharedMemorySize, KSMEM);
    cudaFuncSetAttribute(qside_kernel, cudaFuncAttributeMaxDynamicSharedMemorySize, QSMEM);

    kside_kernel<<<KBLOCKS, 256, KSMEM>>>(k, v, P);
    reduce_kernel<<<65, 256>>>();
    qside_kernel<<<NTILES / 2, 512, QSMEM>>>(q, P, out);
}

// round 16
// speedup vs baseline: 1.1091x; 1.1091x over previous
#include <cuda_runtime.h>
#include <cuda_bf16.h>
#include <cstdint>

typedef unsigned int u32;

#define NORM 0.35355339059327379f   // 64^-0.25
#define RATIO 0.0625f               // 256^-0.5
#define TILE 128
#define NTILES 512
#define KBLOCKS 148

// scratch (allocation-free rule)
__device__ float g_zT[65 * 256];               // [n(0..64)][feat]; row 64 = ksum
__device__ __nv_bfloat16 g_zbh[72 * 256];      // bf16 split of zT (rows 65..71 = 0)
__device__ __nv_bfloat16 g_zbl[72 * 256];

// ---------------- helpers ----------------
__device__ __forceinline__ u32 smem_u32(const void* p) {
    u32 a; asm("{ .reg .u64 t; cvta.to.shared.u64 t, %1; cvt.u32.u64 %0, t; }" : "=r"(a) : "l"(p)); return a;
}
__device__ __forceinline__ void mma_bf16(float* d, const u32* a, const u32* b) {
    asm volatile(
        "mma.sync.aligned.m16n8k16.row.col.f32.bf16.bf16.f32 "
        "{%0,%1,%2,%3}, {%4,%5,%6,%7}, {%8,%9}, {%0,%1,%2,%3};"
        : "+f"(d[0]), "+f"(d[1]), "+f"(d[2]), "+f"(d[3])
        : "r"(a[0]), "r"(a[1]), "r"(a[2]), "r"(a[3]), "r"(b[0]), "r"(b[1]));
}
__device__ __forceinline__ void ldmx2t(u32& r0, u32& r1, u32 addr) {
    asm volatile("ldmatrix.sync.aligned.m8n8.x2.trans.shared.b16 {%0,%1}, [%2];"
        : "=r"(r0), "=r"(r1) : "r"(addr));
}
__device__ __forceinline__ void split2(float x, float y, u32& h, u32& l) {
    __nv_bfloat162 hh = __floats2bfloat162_rn(x, y);
    float2 hf = __bfloat1622float2(hh);
    __nv_bfloat162 ll = __floats2bfloat162_rn(x - hf.x, y - hf.y);
    h = *reinterpret_cast<u32*>(&hh);
    l = *reinterpret_cast<u32*>(&ll);
}
__device__ __forceinline__ void split1(float x, uint16_t& h, uint16_t& l) {
    __nv_bfloat16 bh = __float2bfloat16(x);
    h = __bfloat16_as_ushort(bh);
    l = __bfloat16_as_ushort(__float2bfloat16(x - __bfloat162float(bh)));
}

// stage [nrows x 64] fp32 (RAW) -> bf16 hi/lo, row stride 144 B; optional sumsq
template<int STEP>
__device__ __forceinline__ void stage64(char* dh, char* dl, const float* src,
                                        int nrows, float* sn, int tid) {
    const float4* sp = reinterpret_cast<const float4*>(src);
    int total = nrows * 16;
    for (int idx = tid; idx < total; idx += STEP) {
        int row = idx >> 4, c4 = idx & 15;
        float4 f = sp[idx];
        if (sn) {
            float ps = f.x * f.x + f.y * f.y + f.z * f.z + f.w * f.w;
#pragma unroll
            for (int s = 8; s >= 1; s >>= 1) ps += __shfl_xor_sync(0xffffffffu, ps, s);
            if ((tid & 15) == 0) sn[row] = ps;
        }
        u32 h0, l0, h1, l1;
        split2(f.x, f.y, h0, l0);
        split2(f.z, f.w, h1, l1);
        *(uint2*)(dh + row * 144 + c4 * 8) = make_uint2(h0, h1);
        *(uint2*)(dl + row * 144 + c4 * 8) = make_uint2(l0, l1);
    }
}

__global__ void zero_kernel() {
    int t = blockIdx.x * blockDim.x + threadIdx.x;
    if (t < 65 * 256) g_zT[t] = 0.0f;
}
__global__ void zsplit_kernel() {
    int t = blockIdx.x * blockDim.x + threadIdx.x;
    if (t >= 72 * 256) return;
    int n = t >> 8;
    float x = (n < 65) ? g_zT[t] : 0.0f;
    __nv_bfloat16 h = __float2bfloat16(x);
    g_zbh[t] = h;
    g_zbl[t] = __float2bfloat16(x - __bfloat162float(h));
}

// ======================= kside: exact R10 form (atomics flush) =======================
#define KS_PTH 0
#define KS_PTL 36864
#define KS_KNH 73728
#define KS_KNL 92160
#define KS_KHH 110592
#define KS_KHL 145408
#define KS_VTH 180224
#define KS_VTL 201984
#define KS_SN  223744
#define KSMEM  224256

__global__ __launch_bounds__(256, 1) void kside_kernel(
    const float* __restrict__ kin, const float* __restrict__ vin,
    const float* __restrict__ proj)
{
    extern __shared__ char sm[];
    const int tid = threadIdx.x;
    const int lane = tid & 31, w = tid >> 5;
    const int g = lane >> 2, tg = lane & 3;
    float* sn = reinterpret_cast<float*>(sm + KS_SN);
    const u32 khh_u = smem_u32(sm) + KS_KHH;
    const u32 khl_u = smem_u32(sm) + KS_KHL;

    stage64<256>(sm + KS_PTH, sm + KS_PTL, proj, 256, nullptr, tid);
    for (int i = tid; i < 16 * 128; i += 256) {
        int n = 64 + (i >> 7), k = i & 127;
        uint16_t hv = (n == 64) ? (uint16_t)0x3F80 : (uint16_t)0;
        *(uint16_t*)(sm + KS_VTH + n * 272 + k * 2) = hv;
        *(uint16_t*)(sm + KS_VTL + n * 272 + k * 2) = 0;
    }

    float zacc[5][4][4];
#pragma unroll
    for (int m = 0; m < 5; m++)
#pragma unroll
        for (int j = 0; j < 4; j++)
#pragma unroll
            for (int r = 0; r < 4; r++) zacc[m][j][r] = 0.0f;

    for (int tile = blockIdx.x; tile < NTILES; tile += KBLOCKS) {
        __syncthreads();
        stage64<256>(sm + KS_KNH, sm + KS_KNL, kin + (size_t)tile * TILE * 64, 128, sn, tid);
        {
            const float4* sp = reinterpret_cast<const float4*>(vin + (size_t)tile * TILE * 64);
            for (int idx = tid; idx < 2048; idx += 256) {
                int row = idx >> 4, c4 = idx & 15;
                float4 f = sp[idx];
                float vv[4] = {f.x, f.y, f.z, f.w};
#pragma unroll
                for (int j = 0; j < 4; j++) {
                    uint16_t h, l; split1(vv[j], h, l);
                    int n = c4 * 4 + j;
                    *(uint16_t*)(sm + KS_VTH + n * 272 + row * 2) = h;
                    *(uint16_t*)(sm + KS_VTL + n * 272 + row * 2) = l;
                }
            }
        }
        __syncthreads();

        for (int h = 0; h < 2; h++) {
            float dD[16][4];
#pragma unroll
            for (int nt = 0; nt < 16; nt++)
#pragma unroll
                for (int r = 0; r < 4; r++) dD[nt][r] = 0.0f;
#pragma unroll
            for (int ks = 0; ks < 4; ks++) {
                u32 ab = (u32)((w * 16 + g) * 144 + ks * 32 + tg * 4);
                u32 ah[4] = { *(u32*)(sm + KS_KNH + ab),       *(u32*)(sm + KS_KNH + ab + 8 * 144),
                              *(u32*)(sm + KS_KNH + ab + 16),  *(u32*)(sm + KS_KNH + ab + 8 * 144 + 16) };
                u32 al[4] = { *(u32*)(sm + KS_KNL + ab),       *(u32*)(sm + KS_KNL + ab + 8 * 144),
                              *(u32*)(sm + KS_KNL + ab + 16),  *(u32*)(sm + KS_KNL + ab + 8 * 144 + 16) };
#pragma unroll
                for (int nt = 0; nt < 16; nt++) {
                    u32 bb = (u32)((h * 128 + nt * 8 + g) * 144 + ks * 32 + tg * 4);
                    u32 bh[2] = { *(u32*)(sm + KS_PTH + bb), *(u32*)(sm + KS_PTH + bb + 16) };
                    u32 bl[2] = { *(u32*)(sm + KS_PTL + bb), *(u32*)(sm + KS_PTL + bb + 16) };
                    mma_bf16(dD[nt], ah, bh);
                    mma_bf16(dD[nt], ah, bl);
                    mma_bf16(dD[nt], al, bh);
                }
            }
            {
                float s0 = sn[w * 16 + g], s1 = sn[w * 16 + 8 + g];
#pragma unroll
                for (int nt = 0; nt < 16; nt++) {
                    float e0 = RATIO * __expf(NORM * dD[nt][0] - 0.0625f * s0);
                    float e1 = RATIO * __expf(NORM * dD[nt][1] - 0.0625f * s0);
                    float e2 = RATIO * __expf(NORM * dD[nt][2] - 0.0625f * s1);
                    float e3 = RATIO * __expf(NORM * dD[nt][3] - 0.0625f * s1);
                    u32 h01, l01, h23, l23;
                    split2(e0, e1, h01, l01);
                    split2(e2, e3, h23, l23);
                    u32 o0 = (u32)((w * 16 + g) * 272 + (nt * 8 + tg * 2) * 2);
                    u32 o1 = (u32)((w * 16 + 8 + g) * 272 + (nt * 8 + tg * 2) * 2);
                    *(u32*)(sm + KS_KHH + o0) = h01;
                    *(u32*)(sm + KS_KHH + o1) = h23;
                    *(u32*)(sm + KS_KHL + o0) = l01;
                    *(u32*)(sm + KS_KHL + o1) = l23;
                }
            }
            __syncthreads();
#pragma unroll
            for (int ks = 0; ks < 8; ks++) {
                u32 bh[2][2], bl[2][2];
#pragma unroll
                for (int j = 0; j < 2; j++) {
                    u32 la = (u32)((ks * 16 + (lane & 15)) * 272 + (w * 16 + j * 8) * 2);
                    ldmx2t(bh[j][0], bh[j][1], khh_u + la);
                    ldmx2t(bl[j][0], bl[j][1], khl_u + la);
                }
#pragma unroll
                for (int mt = 0; mt < 5; mt++) {
                    u32 ab = (u32)((mt * 16 + g) * 272 + ks * 32 + tg * 4);
                    u32 ah[4] = { *(u32*)(sm + KS_VTH + ab),      *(u32*)(sm + KS_VTH + ab + 8 * 272),
                                  *(u32*)(sm + KS_VTH + ab + 16), *(u32*)(sm + KS_VTH + ab + 8 * 272 + 16) };
                    u32 al[4] = { *(u32*)(sm + KS_VTL + ab),      *(u32*)(sm + KS_VTL + ab + 8 * 272),
                                  *(u32*)(sm + KS_VTL + ab + 16), *(u32*)(sm + KS_VTL + ab + 8 * 272 + 16) };
#pragma unroll
                    for (int j = 0; j < 2; j++) {
                        float* acc = zacc[mt][h * 2 + j];
                        mma_bf16(acc, ah, bh[j]);
                        mma_bf16(acc, ah, bl[j]);
                        mma_bf16(acc, al, bh[j]);
                    }
                }
            }
            __syncthreads();
        }
    }

#pragma unroll
    for (int mt = 0; mt < 5; mt++) {
        int vn0 = mt * 16 + g, vn1 = vn0 + 8;
#pragma unroll
        for (int jj = 0; jj < 4; jj++) {
            int f0 = (jj >> 1) * 128 + w * 16 + (jj & 1) * 8 + tg * 2;
            if (vn0 < 65) {
                atomicAdd(&g_zT[vn0 * 256 + f0],     zacc[mt][jj][0]);
                atomicAdd(&g_zT[vn0 * 256 + f0 + 1], zacc[mt][jj][1]);
            }
            if (vn1 < 65) {
                atomicAdd(&g_zT[vn1 * 256 + f0],     zacc[mt][jj][2]);
                atomicAdd(&g_zT[vn1 * 256 + f0 + 1], zacc[mt][jj][3]);
            }
        }
    }
}

// ======================= qside: R15 form (512 threads, 2 row-tiles/block) =======================
#define QS_PTH 0
#define QS_PTL 36864
#define QS_QNH 73728
#define QS_QNL 92160
#define QS_ZH  110592
#define QS_ZL  148608
#define QS_SN  186624
#define QSMEM  187136

__global__ __launch_bounds__(512, 1) void qside_kernel(
    const float* __restrict__ qin, const float* __restrict__ proj,
    float* __restrict__ out)
{
    extern __shared__ char sm[];
    const int tid = threadIdx.x;
    const int lane = tid & 31, w = tid >> 5;
    const int g = lane >> 2, tg = lane & 3;
    const int wr = w & 7, wh = w >> 3;
    float* sn = reinterpret_cast<float*>(sm + QS_SN);

    stage64<512>(sm + QS_PTH, sm + QS_PTL, proj, 256, nullptr, tid);
    for (int i = tid; i < 72 * 128; i += 512) {
        int n = i >> 7, c = i & 127;
        *(u32*)(sm + QS_ZH + n * 528 + c * 4) = reinterpret_cast<const u32*>(g_zbh)[i];
        *(u32*)(sm + QS_ZL + n * 528 + c * 4) = reinterpret_cast<const u32*>(g_zbl)[i];
    }

    for (int it = 0; it < 2; it++) {
        const int tile = blockIdx.x * 2 + it;
        __syncthreads();
        stage64<512>(sm + QS_QNH, sm + QS_QNL, qin + (size_t)tile * TILE * 64, 128, sn, tid);
        __syncthreads();

        float wD[9][4];
#pragma unroll
        for (int nt = 0; nt < 9; nt++)
#pragma unroll
            for (int r = 0; r < 4; r++) wD[nt][r] = 0.0f;

        const float s0 = sn[wr * 16 + g], s1 = sn[wr * 16 + 8 + g];

#pragma unroll
        for (int chunk = 0; chunk < 2; chunk++) {
            const int fbase = wh * 128 + chunk * 64;
            float dD[8][4];
#pragma unroll
            for (int nt = 0; nt < 8; nt++)
#pragma unroll
                for (int r = 0; r < 4; r++) dD[nt][r] = 0.0f;
#pragma unroll
            for (int ks = 0; ks < 4; ks++) {
                u32 ab = (u32)((wr * 16 + g) * 144 + ks * 32 + tg * 4);
                u32 ah[4] = { *(u32*)(sm + QS_QNH + ab),      *(u32*)(sm + QS_QNH + ab + 8 * 144),
                              *(u32*)(sm + QS_QNH + ab + 16), *(u32*)(sm + QS_QNH + ab + 8 * 144 + 16) };
                u32 al[4] = { *(u32*)(sm + QS_QNL + ab),      *(u32*)(sm + QS_QNL + ab + 8 * 144),
                              *(u32*)(sm + QS_QNL + ab + 16), *(u32*)(sm + QS_QNL + ab + 8 * 144 + 16) };
#pragma unroll
                for (int nt = 0; nt < 8; nt++) {
                    u32 bb = (u32)((fbase + nt * 8 + g) * 144 + ks * 32 + tg * 4);
                    u32 bh[2] = { *(u32*)(sm + QS_PTH + bb), *(u32*)(sm + QS_PTH + bb + 16) };
                    u32 bl[2] = { *(u32*)(sm + QS_PTL + bb), *(u32*)(sm + QS_PTL + bb + 16) };
                    mma_bf16(dD[nt], ah, bh);
                    mma_bf16(dD[nt], ah, bl);
                    mma_bf16(dD[nt], al, bh);
                }
            }
            u32 qh0[8], qh1[8], ql0[8], ql1[8];
#pragma unroll
            for (int nt = 0; nt < 8; nt++) {
                float e0 = RATIO * __expf(NORM * dD[nt][0] - 0.0625f * s0);
                float e1 = RATIO * __expf(NORM * dD[nt][1] - 0.0625f * s0);
                float e2 = RATIO * __expf(NORM * dD[nt][2] - 0.0625f * s1);
                float e3 = RATIO * __expf(NORM * dD[nt][3] - 0.0625f * s1);
                split2(e0, e1, qh0[nt], ql0[nt]);
                split2(e2, e3, qh1[nt], ql1[nt]);
            }
#pragma unroll
            for (int ks = 0; ks < 4; ks++) {
                u32 ah[4] = { qh0[2 * ks], qh1[2 * ks], qh0[2 * ks + 1], qh1[2 * ks + 1] };
                u32 al[4] = { ql0[2 * ks], ql1[2 * ks], ql0[2 * ks + 1], ql1[2 * ks + 1] };
                u32 kb = (u32)(fbase + ks * 16) * 2;
#pragma unroll
                for (int nt = 0; nt < 9; nt++) {
                    u32 bb = (u32)((nt * 8 + g) * 528) + kb + tg * 4;
                    u32 bh[2] = { *(u32*)(sm + QS_ZH + bb), *(u32*)(sm + QS_ZH + bb + 16) };
                    u32 bl[2] = { *(u32*)(sm + QS_ZL + bb), *(u32*)(sm + QS_ZL + bb + 16) };
                    mma_bf16(wD[nt], ah, bh);
                    mma_bf16(wD[nt], ah, bl);
                    mma_bf16(wD[nt], al, bh);
                }
            }
        }

        __syncthreads();
        float* scratch = reinterpret_cast<float*>(sm + QS_QNH);
        if (wh == 1) {
            float4* sp = reinterpret_cast<float4*>(&scratch[(wr * 32 + lane) * 36]);
#pragma unroll
            for (int nt = 0; nt < 9; nt++)
                sp[nt] = make_float4(wD[nt][0], wD[nt][1], wD[nt][2], wD[nt][3]);
        }
        __syncthreads();
        if (wh == 0) {
            const float4* sp = reinterpret_cast<const float4*>(&scratch[(wr * 32 + lane) * 36]);
#pragma unroll
            for (int nt = 0; nt < 9; nt++) {
                float4 p = sp[nt];
                wD[nt][0] += p.x; wD[nt][1] += p.y; wD[nt][2] += p.z; wD[nt][3] += p.w;
            }
            float den0 = __shfl_sync(0xffffffffu, wD[8][0], lane & 0x1C);
            float den1 = __shfl_sync(0xffffffffu, wD[8][2], lane & 0x1C);
            float di0 = 1.0f / den0, di1 = 1.0f / den1;
            size_t row0 = (size_t)tile * TILE + wr * 16 + g;
            float* ob = out + row0 * 64 + tg * 2;
#pragma unroll
            for (int nt = 0; nt < 8; nt++) {
                *(float2*)(ob + nt * 8)          = make_float2(wD[nt][0] * di0, wD[nt][1] * di0);
                *(float2*)(ob + 8 * 64 + nt * 8) = make_float2(wD[nt][2] * di1, wD[nt][3] * di1);
            }
        }
    }
}

extern "C" void kernel_launch(void* const* d_in, const int* in_sizes, int n_in,
                              void* d_out, int out_size) {
    const float* q = (const float*)d_in[0];
    const float* k = (const float*)d_in[1];
    const float* v = (const float*)d_in[2];
    const float* P = (const float*)d_in[3];
    float* out = (float*)d_out;
    (void)in_sizes; (void)n_in; (void)out_size;

    cudaFuncSetAttribute(kside_kernel, cudaFuncAttributeMaxDynamicSharedMemorySize, KSMEM);
    cudaFuncSetAttribute(qside_kernel, cudaFuncAttributeMaxDynamicSharedMemorySize, QSMEM);

    zero_kernel<<<65, 256>>>();
    kside_kernel<<<KBLOCKS, 256, KSMEM>>>(k, v, P);
    zsplit_kernel<<<72, 256>>>();
    qside_kernel<<<NTILES / 2, 512, QSMEM>>>(q, P, out);
}

// round 17
// speedup vs baseline: 1.1581x; 1.0442x over previous
#include <cuda_runtime.h>
#include <cuda_bf16.h>
#include <cstdint>

typedef unsigned int u32;

#define NORM 0.35355339059327379f   // 64^-0.25
#define RATIO 0.0625f               // 256^-0.5
#define TILE 128
#define NTILES 512
#define KBLOCKS 148

// scratch (allocation-free rule)
__device__ float g_zT[65 * 256];               // [n(0..64)][feat]; row 64 = ksum

// ---------------- helpers ----------------
__device__ __forceinline__ u32 smem_u32(const void* p) {
    u32 a; asm("{ .reg .u64 t; cvta.to.shared.u64 t, %1; cvt.u32.u64 %0, t; }" : "=r"(a) : "l"(p)); return a;
}
__device__ __forceinline__ void mma_bf16(float* d, const u32* a, const u32* b) {
    asm volatile(
        "mma.sync.aligned.m16n8k16.row.col.f32.bf16.bf16.f32 "
        "{%0,%1,%2,%3}, {%4,%5,%6,%7}, {%8,%9}, {%0,%1,%2,%3};"
        : "+f"(d[0]), "+f"(d[1]), "+f"(d[2]), "+f"(d[3])
        : "r"(a[0]), "r"(a[1]), "r"(a[2]), "r"(a[3]), "r"(b[0]), "r"(b[1]));
}
__device__ __forceinline__ void ldmx2t(u32& r0, u32& r1, u32 addr) {
    asm volatile("ldmatrix.sync.aligned.m8n8.x2.trans.shared.b16 {%0,%1}, [%2];"
        : "=r"(r0), "=r"(r1) : "r"(addr));
}
__device__ __forceinline__ void split2(float x, float y, u32& h, u32& l) {
    __nv_bfloat162 hh = __floats2bfloat162_rn(x, y);
    float2 hf = __bfloat1622float2(hh);
    __nv_bfloat162 ll = __floats2bfloat162_rn(x - hf.x, y - hf.y);
    h = *reinterpret_cast<u32*>(&hh);
    l = *reinterpret_cast<u32*>(&ll);
}
__device__ __forceinline__ void split1(float x, uint16_t& h, uint16_t& l) {
    __nv_bfloat16 bh = __float2bfloat16(x);
    h = __bfloat16_as_ushort(bh);
    l = __bfloat16_as_ushort(__float2bfloat16(x - __bfloat162float(bh)));
}

// stage [nrows x 64] fp32 (RAW) -> bf16 hi/lo, row stride 144 B; optional sumsq
template<int STEP>
__device__ __forceinline__ void stage64(char* dh, char* dl, const float* src,
                                        int nrows, float* sn, int tid) {
    const float4* sp = reinterpret_cast<const float4*>(src);
    int total = nrows * 16;
    for (int idx = tid; idx < total; idx += STEP) {
        int row = idx >> 4, c4 = idx & 15;
        float4 f = sp[idx];
        if (sn) {
            float ps = f.x * f.x + f.y * f.y + f.z * f.z + f.w * f.w;
#pragma unroll
            for (int s = 8; s >= 1; s >>= 1) ps += __shfl_xor_sync(0xffffffffu, ps, s);
            if ((tid & 15) == 0) sn[row] = ps;
        }
        u32 h0, l0, h1, l1;
        split2(f.x, f.y, h0, l0);
        split2(f.z, f.w, h1, l1);
        *(uint2*)(dh + row * 144 + c4 * 8) = make_uint2(h0, h1);
        *(uint2*)(dl + row * 144 + c4 * 8) = make_uint2(l0, l1);
    }
}

__global__ void zero_kernel() {
    int t = blockIdx.x * blockDim.x + threadIdx.x;
    if (t < 65 * 256) g_zT[t] = 0.0f;
}

// ======================= kside: R16 form (atomics flush) =======================
#define KS_PTH 0
#define KS_PTL 36864
#define KS_KNH 73728
#define KS_KNL 92160
#define KS_KHH 110592
#define KS_KHL 145408
#define KS_VTH 180224
#define KS_VTL 201984
#define KS_SN  223744
#define KSMEM  224256

__global__ __launch_bounds__(256, 1) void kside_kernel(
    const float* __restrict__ kin, const float* __restrict__ vin,
    const float* __restrict__ proj)
{
    extern __shared__ char sm[];
    const int tid = threadIdx.x;
    const int lane = tid & 31, w = tid >> 5;
    const int g = lane >> 2, tg = lane & 3;
    float* sn = reinterpret_cast<float*>(sm + KS_SN);
    const u32 khh_u = smem_u32(sm) + KS_KHH;
    const u32 khl_u = smem_u32(sm) + KS_KHL;

    stage64<256>(sm + KS_PTH, sm + KS_PTL, proj, 256, nullptr, tid);
    for (int i = tid; i < 16 * 128; i += 256) {
        int n = 64 + (i >> 7), k = i & 127;
        uint16_t hv = (n == 64) ? (uint16_t)0x3F80 : (uint16_t)0;
        *(uint16_t*)(sm + KS_VTH + n * 272 + k * 2) = hv;
        *(uint16_t*)(sm + KS_VTL + n * 272 + k * 2) = 0;
    }

    float zacc[5][4][4];
#pragma unroll
    for (int m = 0; m < 5; m++)
#pragma unroll
        for (int j = 0; j < 4; j++)
#pragma unroll
            for (int r = 0; r < 4; r++) zacc[m][j][r] = 0.0f;

    for (int tile = blockIdx.x; tile < NTILES; tile += KBLOCKS) {
        __syncthreads();
        stage64<256>(sm + KS_KNH, sm + KS_KNL, kin + (size_t)tile * TILE * 64, 128, sn, tid);
        {
            const float4* sp = reinterpret_cast<const float4*>(vin + (size_t)tile * TILE * 64);
            for (int idx = tid; idx < 2048; idx += 256) {
                int row = idx >> 4, c4 = idx & 15;
                float4 f = sp[idx];
                float vv[4] = {f.x, f.y, f.z, f.w};
#pragma unroll
                for (int j = 0; j < 4; j++) {
                    uint16_t h, l; split1(vv[j], h, l);
                    int n = c4 * 4 + j;
                    *(uint16_t*)(sm + KS_VTH + n * 272 + row * 2) = h;
                    *(uint16_t*)(sm + KS_VTL + n * 272 + row * 2) = l;
                }
            }
        }
        __syncthreads();

        for (int h = 0; h < 2; h++) {
            float dD[16][4];
#pragma unroll
            for (int nt = 0; nt < 16; nt++)
#pragma unroll
                for (int r = 0; r < 4; r++) dD[nt][r] = 0.0f;
#pragma unroll
            for (int ks = 0; ks < 4; ks++) {
                u32 ab = (u32)((w * 16 + g) * 144 + ks * 32 + tg * 4);
                u32 ah[4] = { *(u32*)(sm + KS_KNH + ab),       *(u32*)(sm + KS_KNH + ab + 8 * 144),
                              *(u32*)(sm + KS_KNH + ab + 16),  *(u32*)(sm + KS_KNH + ab + 8 * 144 + 16) };
                u32 al[4] = { *(u32*)(sm + KS_KNL + ab),       *(u32*)(sm + KS_KNL + ab + 8 * 144),
                              *(u32*)(sm + KS_KNL + ab + 16),  *(u32*)(sm + KS_KNL + ab + 8 * 144 + 16) };
#pragma unroll
                for (int nt = 0; nt < 16; nt++) {
                    u32 bb = (u32)((h * 128 + nt * 8 + g) * 144 + ks * 32 + tg * 4);
                    u32 bh[2] = { *(u32*)(sm + KS_PTH + bb), *(u32*)(sm + KS_PTH + bb + 16) };
                    u32 bl[2] = { *(u32*)(sm + KS_PTL + bb), *(u32*)(sm + KS_PTL + bb + 16) };
                    mma_bf16(dD[nt], ah, bh);
                    mma_bf16(dD[nt], ah, bl);
                    mma_bf16(dD[nt], al, bh);
                }
            }
            {
                float s0 = sn[w * 16 + g], s1 = sn[w * 16 + 8 + g];
#pragma unroll
                for (int nt = 0; nt < 16; nt++) {
                    float e0 = RATIO * __expf(NORM * dD[nt][0] - 0.0625f * s0);
                    float e1 = RATIO * __expf(NORM * dD[nt][1] - 0.0625f * s0);
                    float e2 = RATIO * __expf(NORM * dD[nt][2] - 0.0625f * s1);
                    float e3 = RATIO * __expf(NORM * dD[nt][3] - 0.0625f * s1);
                    u32 h01, l01, h23, l23;
                    split2(e0, e1, h01, l01);
                    split2(e2, e3, h23, l23);
                    u32 o0 = (u32)((w * 16 + g) * 272 + (nt * 8 + tg * 2) * 2);
                    u32 o1 = (u32)((w * 16 + 8 + g) * 272 + (nt * 8 + tg * 2) * 2);
                    *(u32*)(sm + KS_KHH + o0) = h01;
                    *(u32*)(sm + KS_KHH + o1) = h23;
                    *(u32*)(sm + KS_KHL + o0) = l01;
                    *(u32*)(sm + KS_KHL + o1) = l23;
                }
            }
            __syncthreads();
#pragma unroll
            for (int ks = 0; ks < 8; ks++) {
                u32 bh[2][2], bl[2][2];
#pragma unroll
                for (int j = 0; j < 2; j++) {
                    u32 la = (u32)((ks * 16 + (lane & 15)) * 272 + (w * 16 + j * 8) * 2);
                    ldmx2t(bh[j][0], bh[j][1], khh_u + la);
                    ldmx2t(bl[j][0], bl[j][1], khl_u + la);
                }
#pragma unroll
                for (int mt = 0; mt < 5; mt++) {
                    u32 ab = (u32)((mt * 16 + g) * 272 + ks * 32 + tg * 4);
                    u32 ah[4] = { *(u32*)(sm + KS_VTH + ab),      *(u32*)(sm + KS_VTH + ab + 8 * 272),
                                  *(u32*)(sm + KS_VTH + ab + 16), *(u32*)(sm + KS_VTH + ab + 8 * 272 + 16) };
                    u32 al[4] = { *(u32*)(sm + KS_VTL + ab),      *(u32*)(sm + KS_VTL + ab + 8 * 272),
                                  *(u32*)(sm + KS_VTL + ab + 16), *(u32*)(sm + KS_VTL + ab + 8 * 272 + 16) };
#pragma unroll
                    for (int j = 0; j < 2; j++) {
                        float* acc = zacc[mt][h * 2 + j];
                        mma_bf16(acc, ah, bh[j]);
                        mma_bf16(acc, ah, bl[j]);
                        mma_bf16(acc, al, bh[j]);
                    }
                }
            }
            __syncthreads();
        }
    }

#pragma unroll
    for (int mt = 0; mt < 5; mt++) {
        int vn0 = mt * 16 + g, vn1 = vn0 + 8;
#pragma unroll
        for (int jj = 0; jj < 4; jj++) {
            int f0 = (jj >> 1) * 128 + w * 16 + (jj & 1) * 8 + tg * 2;
            if (vn0 < 65) {
                atomicAdd(&g_zT[vn0 * 256 + f0],     zacc[mt][jj][0]);
                atomicAdd(&g_zT[vn0 * 256 + f0 + 1], zacc[mt][jj][1]);
            }
            if (vn1 < 65) {
                atomicAdd(&g_zT[vn1 * 256 + f0],     zacc[mt][jj][2]);
                atomicAdd(&g_zT[vn1 * 256 + f0 + 1], zacc[mt][jj][3]);
            }
        }
    }
}

// ======================= qside: persistent 148 blocks, inline z split =======================
#define QS_PTH 0
#define QS_PTL 36864
#define QS_QNH 73728
#define QS_QNL 92160
#define QS_ZH  110592
#define QS_ZL  148608
#define QS_SN  186624
#define QSMEM  187136

__global__ __launch_bounds__(512, 1) void qside_kernel(
    const float* __restrict__ qin, const float* __restrict__ proj,
    float* __restrict__ out)
{
    extern __shared__ char sm[];
    const int tid = threadIdx.x;
    const int lane = tid & 31, w = tid >> 5;
    const int g = lane >> 2, tg = lane & 3;
    const int wr = w & 7, wh = w >> 3;
    float* sn = reinterpret_cast<float*>(sm + QS_SN);

    // stage P once per block
    stage64<512>(sm + QS_PTH, sm + QS_PTL, proj, 256, nullptr, tid);
    // stage zT once per block: read g_zT fp32, split inline (rows 65..71 zero)
    for (int i = tid; i < 72 * 128; i += 512) {
        int n = i >> 7, c = i & 127;
        u32 h, l;
        if (n < 65) {
            float2 zv = *reinterpret_cast<const float2*>(&g_zT[n * 256 + c * 2]);
            split2(zv.x, zv.y, h, l);
        } else { h = 0u; l = 0u; }
        *(u32*)(sm + QS_ZH + n * 528 + c * 4) = h;
        *(u32*)(sm + QS_ZL + n * 528 + c * 4) = l;
    }

    for (int tile = blockIdx.x; tile < NTILES; tile += KBLOCKS) {
        __syncthreads();   // orders scratch reads (prev iter) before qn restage
        stage64<512>(sm + QS_QNH, sm + QS_QNL, qin + (size_t)tile * TILE * 64, 128, sn, tid);
        __syncthreads();

        float wD[9][4];
#pragma unroll
        for (int nt = 0; nt < 9; nt++)
#pragma unroll
            for (int r = 0; r < 4; r++) wD[nt][r] = 0.0f;

        const float s0 = sn[wr * 16 + g], s1 = sn[wr * 16 + 8 + g];

#pragma unroll
        for (int chunk = 0; chunk < 2; chunk++) {
            const int fbase = wh * 128 + chunk * 64;
            float dD[8][4];
#pragma unroll
            for (int nt = 0; nt < 8; nt++)
#pragma unroll
                for (int r = 0; r < 4; r++) dD[nt][r] = 0.0f;
#pragma unroll
            for (int ks = 0; ks < 4; ks++) {
                u32 ab = (u32)((wr * 16 + g) * 144 + ks * 32 + tg * 4);
                u32 ah[4] = { *(u32*)(sm + QS_QNH + ab),      *(u32*)(sm + QS_QNH + ab + 8 * 144),
                              *(u32*)(sm + QS_QNH + ab + 16), *(u32*)(sm + QS_QNH + ab + 8 * 144 + 16) };
                u32 al[4] = { *(u32*)(sm + QS_QNL + ab),      *(u32*)(sm + QS_QNL + ab + 8 * 144),
                              *(u32*)(sm + QS_QNL + ab + 16), *(u32*)(sm + QS_QNL + ab + 8 * 144 + 16) };
#pragma unroll
                for (int nt = 0; nt < 8; nt++) {
                    u32 bb = (u32)((fbase + nt * 8 + g) * 144 + ks * 32 + tg * 4);
                    u32 bh[2] = { *(u32*)(sm + QS_PTH + bb), *(u32*)(sm + QS_PTH + bb + 16) };
                    u32 bl[2] = { *(u32*)(sm + QS_PTL + bb), *(u32*)(sm + QS_PTL + bb + 16) };
                    mma_bf16(dD[nt], ah, bh);
                    mma_bf16(dD[nt], ah, bl);
                    mma_bf16(dD[nt], al, bh);
                }
            }
            u32 qh0[8], qh1[8], ql0[8], ql1[8];
#pragma unroll
            for (int nt = 0; nt < 8; nt++) {
                float e0 = RATIO * __expf(NORM * dD[nt][0] - 0.0625f * s0);
                float e1 = RATIO * __expf(NORM * dD[nt][1] - 0.0625f * s0);
                float e2 = RATIO * __expf(NORM * dD[nt][2] - 0.0625f * s1);
                float e3 = RATIO * __expf(NORM * dD[nt][3] - 0.0625f * s1);
                split2(e0, e1, qh0[nt], ql0[nt]);
                split2(e2, e3, qh1[nt], ql1[nt]);
            }
#pragma unroll
            for (int ks = 0; ks < 4; ks++) {
                u32 ah[4] = { qh0[2 * ks], qh1[2 * ks], qh0[2 * ks + 1], qh1[2 * ks + 1] };
                u32 al[4] = { ql0[2 * ks], ql1[2 * ks], ql0[2 * ks + 1], ql1[2 * ks + 1] };
                u32 kb = (u32)(fbase + ks * 16) * 2;
#pragma unroll
                for (int nt = 0; nt < 9; nt++) {
                    u32 bb = (u32)((nt * 8 + g) * 528) + kb + tg * 4;
                    u32 bh[2] = { *(u32*)(sm + QS_ZH + bb), *(u32*)(sm + QS_ZH + bb + 16) };
                    u32 bl[2] = { *(u32*)(sm + QS_ZL + bb), *(u32*)(sm + QS_ZL + bb + 16) };
                    mma_bf16(wD[nt], ah, bh);
                    mma_bf16(wD[nt], ah, bl);
                    mma_bf16(wD[nt], al, bh);
                }
            }
        }

        // ---- cross-half reduction (scratch aliases dead qn region) ----
        __syncthreads();
        float* scratch = reinterpret_cast<float*>(sm + QS_QNH);
        if (wh == 1) {
            float4* sp = reinterpret_cast<float4*>(&scratch[(wr * 32 + lane) * 36]);
#pragma unroll
            for (int nt = 0; nt < 9; nt++)
                sp[nt] = make_float4(wD[nt][0], wD[nt][1], wD[nt][2], wD[nt][3]);
        }
        __syncthreads();
        if (wh == 0) {
            const float4* sp = reinterpret_cast<const float4*>(&scratch[(wr * 32 + lane) * 36]);
#pragma unroll
            for (int nt = 0; nt < 9; nt++) {
                float4 p = sp[nt];
                wD[nt][0] += p.x; wD[nt][1] += p.y; wD[nt][2] += p.z; wD[nt][3] += p.w;
            }
            float den0 = __shfl_sync(0xffffffffu, wD[8][0], lane & 0x1C);
            float den1 = __shfl_sync(0xffffffffu, wD[8][2], lane & 0x1C);
            float di0 = 1.0f / den0, di1 = 1.0f / den1;
            size_t row0 = (size_t)tile * TILE + wr * 16 + g;
            float* ob = out + row0 * 64 + tg * 2;
#pragma unroll
            for (int nt = 0; nt < 8; nt++) {
                *(float2*)(ob + nt * 8)          = make_float2(wD[nt][0] * di0, wD[nt][1] * di0);
                *(float2*)(ob + 8 * 64 + nt * 8) = make_float2(wD[nt][2] * di1, wD[nt][3] * di1);
            }
        }
    }
}

extern "C" void kernel_launch(void* const* d_in, const int* in_sizes, int n_in,
                              void* d_out, int out_size) {
    const float* q = (const float*)d_in[0];
    const float* k = (const float*)d_in[1];
    const float* v = (const float*)d_in[2];
    const float* P = (const float*)d_in[3];
    float* out = (float*)d_out;
    (void)in_sizes; (void)n_in; (void)out_size;

    cudaFuncSetAttribute(kside_kernel, cudaFuncAttributeMaxDynamicSharedMemorySize, KSMEM);
    cudaFuncSetAttribute(qside_kernel, cudaFuncAttributeMaxDynamicSharedMemorySize, QSMEM);

    zero_kernel<<<65, 256>>>();
    kside_kernel<<<KBLOCKS, 256, KSMEM>>>(k, v, P);
    qside_kernel<<<KBLOCKS, 512, QSMEM>>>(q, P, out);
}